// round 7
// baseline (speedup 1.0000x reference)
#include <cuda_runtime.h>
#include <cuda_fp16.h>
#include <math.h>

#define BSZ 2
#define NP  2048
#define CH  256
#define FFNC 1024
#define NROW (BSZ*NP)
#define NBLK 256           // persistent IPOT grid (128 per batch, 16 rows each)

// ---------------- scratch (device globals; no allocations) ----------------
__device__ __half g_Qh[(size_t)BSZ*NP*NP];   // IPOT transport matrix (fp16), in place
__device__ __half g_Gh[(size_t)BSZ*NP*NP];   // exp(-cost/10) (fp16)
__device__ float g_Xtp[(size_t)BSZ*NP*CH];   // pts feat transposed [b,n,c]
__device__ float g_Xti[(size_t)BSZ*NP*CH];   // img feat transposed [b,n,c]
__device__ float g_imf[(size_t)BSZ*CH*NP];   // img projected feat [b,c,m] (pre-scaled by b)
__device__ float g_xcat[(size_t)BSZ*NP*2*CH];// [pf ; img_att] token-major [b,n,512]
__device__ float g_x[(size_t)BSZ*NP*CH];     // post out-proj (+LN in place)
__device__ float g_h[(size_t)BSZ*NP*FFNC];   // FFN hidden
__device__ float g_y2[(size_t)BSZ*NP*CH];    // FFN out + residual
__device__ float g_pcls[NROW], g_icls[NROW];
__device__ float g_bv[NROW], g_wv[NROW];
__device__ float g_v[3][NROW];               // triple-buffered column sums v = Q^T a

// grid-barrier state (zero-initialized; g_gen monotonic across replays)
__device__ unsigned g_cnt8[8];
__device__ unsigned g_cntm;
__device__ volatile unsigned g_gen;

// ---------------- software grid barrier (all NBLK CTAs co-resident) ----------------
__device__ __forceinline__ void gridbar() {
    __syncthreads();
    if (threadIdx.x == 0) {
        unsigned my = g_gen;
        __threadfence();
        unsigned s = blockIdx.x & 7;                 // 8 groups of 32
        if (atomicAdd(&g_cnt8[s], 1) == 31) {
            g_cnt8[s] = 0;
            if (atomicAdd(&g_cntm, 1) == 7) {
                g_cntm = 0;
                __threadfence();
                g_gen = my + 1;
            }
        }
        while (g_gen == my) { __nanosleep(64); }
        __threadfence();
    }
    __syncthreads();
}

// ---------------- transpose [b,C,N] -> [b,N,C] ----------------
__global__ void k_transpose(const float* __restrict__ src, int which) {
    __shared__ float t[32][33];
    int b = blockIdx.z;
    float* dst = which ? g_Xti : g_Xtp;
    const float* s = src + (size_t)b * CH * NP;
    float* d = dst + (size_t)b * NP * CH;
    int n0 = blockIdx.x * 32, c0 = blockIdx.y * 32;
    for (int i = threadIdx.y; i < 32; i += 8)
        t[i][threadIdx.x] = s[(size_t)(c0 + i) * NP + n0 + threadIdx.x];
    __syncthreads();
    for (int i = threadIdx.y; i < 32; i += 8)
        d[(size_t)(n0 + i) * CH + c0 + threadIdx.x] = t[threadIdx.x][i];
}

// ---------------- pcls/icls = sigmoid(max over classes) ----------------
__global__ void k_cls(const float* __restrict__ pc, const float* __restrict__ ic) {
    int idx = blockIdx.x * 256 + threadIdx.x;   // 0..4095
    int b = idx >> 11, n = idx & (NP - 1);
    const float* p = pc + (size_t)b * 10 * NP + n;
    const float* q = ic + (size_t)b * 10 * NP + n;
    float mp = -1e30f, mi = -1e30f;
    #pragma unroll
    for (int c = 0; c < 10; c++) {
        mp = fmaxf(mp, p[(size_t)c * NP]);
        mi = fmaxf(mi, q[(size_t)c * NP]);
    }
    g_pcls[idx] = 1.f / (1.f + expf(-mp));
    g_icls[idx] = 1.f / (1.f + expf(-mi));
}

// ---------------- persistent IPOT: all 100 iterations in one kernel ----------------
// 256 CTAs (128/batch, block owns 16 consecutive rows). Thread owns columns
// tid*8..tid*8+7 for ALL rows: column partials live in 8 registers, flushed with
// 8 spread atomics/iter. Per row: 2 LDG.128 + STG.128, warp shfl-reduce + one
// __syncthreads (pipelined: row r+2 loads issue before row r's sync).
__global__ void __launch_bounds__(256, 2) k_ipot_persist(
    const float* __restrict__ ppos, const float* __restrict__ ipos) {
    __shared__ float uw[2][8];
    __shared__ float pcls_s[16];
    int tid = threadIdx.x, lane = tid & 31, wid = tid >> 5;
    int bid = blockIdx.x;
    int batch = bid >> 7, lb = bid & 127;
    int boff = batch * NP;
    int row0 = lb * 16;
    int c0 = tid * 8;

    if (tid < 16) pcls_s[tid] = g_pcls[boff + row0 + tid];
    // icls for my 8 columns (constant across iterations)
    float icz[8];
    {
        float4 i0 = *(const float4*)(g_icls + boff + c0);
        float4 i1 = *(const float4*)(g_icls + boff + c0 + 4);
        icz[0]=i0.x; icz[1]=i0.y; icz[2]=i0.z; icz[3]=i0.w;
        icz[4]=i1.x; icz[5]=i1.y; icz[6]=i1.z; icz[7]=i1.w;
    }
    float an_prev[16];
    #pragma unroll
    for (int r = 0; r < 16; r++) an_prev[r] = 0.f;

    const __half* Gb = g_Gh + (size_t)(boff + row0) * NP + c0;
    __half* Qb = g_Qh + (size_t)(boff + row0) * NP + c0;

    // prologue: zero v[1] (t=1 target), 16 cols per block
    if (tid < 16) g_v[1][boff + lb * 16 + tid] = 0.f;
    __syncthreads();
    gridbar();

    for (int t = 1; t <= 100; t++) {
        // b for my 8 columns
        float bz[8];
        if (t == 1) {
            #pragma unroll
            for (int h = 0; h < 8; h++) bz[h] = 1.0f / NP;
        } else {
            const float* vr = g_v[(t - 1) % 3] + boff + c0;
            float4 v0 = __ldcg((const float4*)vr);
            float4 v1 = __ldcg((const float4*)(vr + 4));
            bz[0] = __fdividef(icz[0], v0.x + 1e-6f);
            bz[1] = __fdividef(icz[1], v0.y + 1e-6f);
            bz[2] = __fdividef(icz[2], v0.z + 1e-6f);
            bz[3] = __fdividef(icz[3], v0.w + 1e-6f);
            bz[4] = __fdividef(icz[4], v1.x + 1e-6f);
            bz[5] = __fdividef(icz[5], v1.y + 1e-6f);
            bz[6] = __fdividef(icz[6], v1.z + 1e-6f);
            bz[7] = __fdividef(icz[7], v1.w + 1e-6f);
        }
        // zero next v buffer (16 cols per block)
        if (tid < 16) g_v[(t + 1) % 3][boff + lb * 16 + tid] = 0.f;

        float vacc[8];
        #pragma unroll
        for (int h = 0; h < 8; h++) vacc[h] = 0.f;

        if (t == 1) {
            // generate G, init Q; same one-sync-per-row structure
            float2 ip2[8];
            #pragma unroll
            for (int h = 0; h < 8; h++) ip2[h] = ((const float2*)ipos)[boff + c0 + h];
            #pragma unroll
            for (int r = 0; r < 16; r++) {
                float2 pp = ((const float2*)ppos)[boff + row0 + r];
                float q[8]; float up = 0.f;
                uint4 go, qo;
                __half2* goh = (__half2*)&go; __half2* qoh = (__half2*)&qo;
                #pragma unroll
                for (int hh = 0; hh < 4; hh++) {
                    float g0, g1;
                    {
                        float dx = pp.x - ip2[2*hh].x, dy = pp.y - ip2[2*hh].y;
                        g0 = expf(-0.1f * sqrtf(dx * dx + dy * dy));
                        dx = pp.x - ip2[2*hh+1].x; dy = pp.y - ip2[2*hh+1].y;
                        g1 = expf(-0.1f * sqrtf(dx * dx + dy * dy));
                    }
                    goh[hh] = __floats2half2_rn(g0, g1);
                    float n0 = fmaxf(g0, 1e-6f), n1 = fmaxf(g1, 1e-6f);
                    qoh[hh] = __floats2half2_rn(n0, n1);
                    q[2*hh] = n0; q[2*hh+1] = n1;
                    up += n0 + n1;
                }
                *(uint4*)(Gb + (size_t)r * NP) = go;   // Gb is const __half*; cast away
                *(uint4*)(Qb + (size_t)r * NP) = qo;
                #pragma unroll
                for (int o = 16; o; o >>= 1) up += __shfl_xor_sync(0xffffffffu, up, o);
                if (lane == 0) uw[r & 1][wid] = up;
                __syncthreads();
                float u = 0.f;
                #pragma unroll
                for (int w = 0; w < 8; w++) u += uw[r & 1][w];
                u *= (1.0f / NP);
                float an = __fdividef(pcls_s[r], u + 1e-6f);
                an_prev[r] = an;
                #pragma unroll
                for (int h = 0; h < 8; h++) vacc[h] += an * q[h];
            }
        } else {
            uint4 gst[2], qst[2];
            gst[0] = *(const uint4*)(Gb);
            qst[0] = *(const uint4*)(Qb);
            gst[1] = *(const uint4*)(Gb + NP);
            qst[1] = *(const uint4*)(Qb + NP);
            #pragma unroll
            for (int r = 0; r < 16; r++) {
                uint4 gc = gst[r & 1], qc = qst[r & 1];
                if (r + 2 < 16) {
                    gst[r & 1] = *(const uint4*)(Gb + (size_t)(r + 2) * NP);
                    qst[r & 1] = *(const uint4*)(Qb + (size_t)(r + 2) * NP);
                }
                float ap = an_prev[r];
                const __half2* gh = (const __half2*)&gc;
                const __half2* qh = (const __half2*)&qc;
                uint4 qo; __half2* qoh = (__half2*)&qo;
                float q[8]; float up = 0.f;
                #pragma unroll
                for (int hh = 0; hh < 4; hh++) {
                    float2 gf = __half22float2(gh[hh]);
                    float2 qf = __half22float2(qh[hh]);
                    float n0 = fmaxf(gf.x * (ap * qf.x * bz[2*hh]), 1e-6f);
                    float n1 = fmaxf(gf.y * (ap * qf.y * bz[2*hh+1]), 1e-6f);
                    qoh[hh] = __floats2half2_rn(n0, n1);
                    q[2*hh] = n0; q[2*hh+1] = n1;
                    up += n0 * bz[2*hh] + n1 * bz[2*hh+1];
                }
                *(uint4*)(Qb + (size_t)r * NP) = qo;
                #pragma unroll
                for (int o = 16; o; o >>= 1) up += __shfl_xor_sync(0xffffffffu, up, o);
                if (lane == 0) uw[r & 1][wid] = up;
                __syncthreads();
                float u = 0.f;
                #pragma unroll
                for (int w = 0; w < 8; w++) u += uw[r & 1][w];
                float an = __fdividef(pcls_s[r], u + 1e-6f);
                an_prev[r] = an;
                #pragma unroll
                for (int h = 0; h < 8; h++) vacc[h] += an * q[h];
            }
        }

        // flush column partials (spread addresses, one lane per address per block)
        float* vw = g_v[t % 3] + boff + c0;
        #pragma unroll
        for (int h = 0; h < 8; h++) atomicAdd(vw + h, vacc[h]);
        gridbar();
    }

    // epilogue: b_final = icls/(v[100%3=1]+eps); lb==0 block stores g_bv
    float bz[8];
    {
        const float* vf = g_v[1] + boff + c0;
        float4 v0 = __ldcg((const float4*)vf);
        float4 v1 = __ldcg((const float4*)(vf + 4));
        bz[0] = __fdividef(icz[0], v0.x + 1e-6f);
        bz[1] = __fdividef(icz[1], v0.y + 1e-6f);
        bz[2] = __fdividef(icz[2], v0.z + 1e-6f);
        bz[3] = __fdividef(icz[3], v0.w + 1e-6f);
        bz[4] = __fdividef(icz[4], v1.x + 1e-6f);
        bz[5] = __fdividef(icz[5], v1.y + 1e-6f);
        bz[6] = __fdividef(icz[6], v1.z + 1e-6f);
        bz[7] = __fdividef(icz[7], v1.w + 1e-6f);
        if (lb == 0) {
            *(float4*)(g_bv + boff + c0)     = make_float4(bz[0], bz[1], bz[2], bz[3]);
            *(float4*)(g_bv + boff + c0 + 4) = make_float4(bz[4], bz[5], bz[6], bz[7]);
        }
    }

    // row-normalization scale w = a / max(a * rowsum(Q*b_final), 1e-12)
    #pragma unroll
    for (int r = 0; r < 16; r++) {
        uint4 qc = *(const uint4*)(Qb + (size_t)r * NP);
        const __half2* qh = (const __half2*)&qc;
        float srs = 0.f;
        #pragma unroll
        for (int hh = 0; hh < 4; hh++) {
            float2 qf = __half22float2(qh[hh]);
            srs += qf.x * bz[2*hh] + qf.y * bz[2*hh+1];
        }
        #pragma unroll
        for (int o = 16; o; o >>= 1) srs += __shfl_xor_sync(0xffffffffu, srs, o);
        if (lane == 0) uw[r & 1][wid] = srs;
        __syncthreads();
        if (tid == 0) {
            float s = 0.f;
            #pragma unroll
            for (int w = 0; w < 8; w++) s += uw[r & 1][w];
            float a = an_prev[r];
            g_wv[boff + row0 + r] = a / fmaxf(a * s, 1e-12f);
        }
    }
}

// ---------------- tiled GEMM 128x128x32, 8x8/thread: C[i,j] = sum_k A[i,k]*B[j,k] ----------------
// MODE 0: pf   A=g_Xtp[b](2048x256)   B=Wp     -> xcat[:, :256] (+bp+bqp+Wqp·ppos(i))
// MODE 1: imf  A=Wi(256x256)          B=g_Xti  -> g_imf[b,c,m]  (+bi+bkp+Wkp·ipos(j)) * bv[j]
// MODE 2: att  A=g_Qh[b] (fp16)       B=g_imf  -> xcat[:,256:]  (*wv[i])
// MODE 3: proj A=g_xcat[b](2048x512)  B=Wout   -> g_x           (+bout)
// MODE 4: ffn1 A=g_x[b](2048x256)     B=Wf1    -> g_h           relu(+bf1)
// MODE 5: ffn2 A=g_h[b](2048x1024)    B=Wf2    -> g_y2          (+bf2 + g_x residual)
template<int MODE>
__global__ void __launch_bounds__(256) k_gemm(const float* __restrict__ e0,
                                              const float* __restrict__ p0,
                                              const float* __restrict__ p1,
                                              const float* __restrict__ p2,
                                              const float* __restrict__ p3) {
    constexpr int BM = 128, BN = 128, BK = 32;
    constexpr int K = (MODE == 0 || MODE == 1 || MODE == 4) ? 256 :
                      (MODE == 2 ? 2048 : (MODE == 3 ? 512 : 1024));
    int b = blockIdx.z;
    const float* A = nullptr; const float* Bm;
    if constexpr (MODE == 0)      { A = g_Xtp + (size_t)b * NP * CH;  Bm = e0; }
    else if constexpr (MODE == 1) { A = e0;                           Bm = g_Xti + (size_t)b * NP * CH; }
    else if constexpr (MODE == 2) { Bm = g_imf + (size_t)b * CH * NP; }
    else if constexpr (MODE == 3) { A = g_xcat + (size_t)b * NP * 2 * CH; Bm = e0; }
    else if constexpr (MODE == 4) { A = g_x + (size_t)b * NP * CH;    Bm = e0; }
    else                          { A = g_h + (size_t)b * NP * FFNC;  Bm = e0; }

    __shared__ float Asm[BK][BM + 4];
    __shared__ float Bsm[BK][BN + 4];
    int i0 = blockIdx.y * BM, j0 = blockIdx.x * BN;
    int tx = threadIdx.x & 15, ty = threadIdx.x >> 4;
    float acc[8][8];
    #pragma unroll
    for (int r = 0; r < 8; r++)
        #pragma unroll
        for (int c = 0; c < 8; c++) acc[r][c] = 0.f;

    for (int k0 = 0; k0 < K; k0 += BK) {
        if constexpr (MODE == 2) {
            const __half* Ah = g_Qh + (size_t)b * NP * NP;
            #pragma unroll
            for (int s = 0; s < 2; s++) {
                int f = threadIdx.x + s * 256;
                int i = f >> 2, k8 = (f & 3) * 8;
                uint4 av = *(const uint4*)(Ah + (size_t)(i0 + i) * K + k0 + k8);
                const __half2* ah = (const __half2*)&av;
                #pragma unroll
                for (int h = 0; h < 4; h++) {
                    float2 af = __half22float2(ah[h]);
                    Asm[k8 + 2 * h][i] = af.x;
                    Asm[k8 + 2 * h + 1][i] = af.y;
                }
            }
        } else {
            #pragma unroll
            for (int s = 0; s < 4; s++) {
                int f4 = threadIdx.x + s * 256;
                int i = f4 >> 3, k4 = f4 & 7;
                float4 v = *(const float4*)(A + (size_t)(i0 + i) * K + k0 + k4 * 4);
                Asm[k4 * 4 + 0][i] = v.x; Asm[k4 * 4 + 1][i] = v.y;
                Asm[k4 * 4 + 2][i] = v.z; Asm[k4 * 4 + 3][i] = v.w;
            }
        }
        #pragma unroll
        for (int s = 0; s < 4; s++) {
            int f4 = threadIdx.x + s * 256;
            int j = f4 >> 3, k4 = f4 & 7;
            float4 v = *(const float4*)(Bm + (size_t)(j0 + j) * K + k0 + k4 * 4);
            Bsm[k4 * 4 + 0][j] = v.x; Bsm[k4 * 4 + 1][j] = v.y;
            Bsm[k4 * 4 + 2][j] = v.z; Bsm[k4 * 4 + 3][j] = v.w;
        }
        __syncthreads();
        #pragma unroll
        for (int kk = 0; kk < BK; kk++) {
            float4 a0 = *(const float4*)&Asm[kk][ty * 8];
            float4 a1 = *(const float4*)&Asm[kk][ty * 8 + 4];
            float4 b0 = *(const float4*)&Bsm[kk][tx * 8];
            float4 b1 = *(const float4*)&Bsm[kk][tx * 8 + 4];
            float ar[8] = {a0.x, a0.y, a0.z, a0.w, a1.x, a1.y, a1.z, a1.w};
            float br[8] = {b0.x, b0.y, b0.z, b0.w, b1.x, b1.y, b1.z, b1.w};
            #pragma unroll
            for (int r = 0; r < 8; r++)
                #pragma unroll
                for (int c = 0; c < 8; c++) acc[r][c] += ar[r] * br[c];
        }
        __syncthreads();
    }

    int j = j0 + tx * 8;
    float bc[8], w0c[8], w1c[8], ppx[8], ppy[8], bvc[8];
    if constexpr (MODE == 0) {
        #pragma unroll
        for (int c = 0; c < 8; c++) {
            bc[c] = p0[j + c] + p1[j + c];
            w0c[c] = p2[2 * (j + c)];
            w1c[c] = p2[2 * (j + c) + 1];
        }
    } else if constexpr (MODE == 1) {
        #pragma unroll
        for (int c = 0; c < 8; c++) {
            float2 pp = ((const float2*)p3)[b * NP + j + c];
            ppx[c] = pp.x; ppy[c] = pp.y;
            bvc[c] = g_bv[b * NP + j + c];
        }
    } else if constexpr (MODE == 3 || MODE == 4 || MODE == 5) {
        #pragma unroll
        for (int c = 0; c < 8; c++) bc[c] = p0[j + c];
    }

    #pragma unroll
    for (int r = 0; r < 8; r++) {
        int i = i0 + ty * 8 + r;
        float vr[8];
        #pragma unroll
        for (int c = 0; c < 8; c++) vr[c] = acc[r][c];
        if constexpr (MODE == 0) {
            float2 pp = ((const float2*)p3)[b * NP + i];
            #pragma unroll
            for (int c = 0; c < 8; c++) vr[c] += bc[c] + w0c[c] * pp.x + w1c[c] * pp.y;
            float* o = g_xcat + ((size_t)(b * NP + i)) * (2 * CH) + j;
            *(float4*)o = make_float4(vr[0], vr[1], vr[2], vr[3]);
            *(float4*)(o + 4) = make_float4(vr[4], vr[5], vr[6], vr[7]);
        } else if constexpr (MODE == 1) {
            float bia = p0[i] + p1[i];
            float w0 = p2[2 * i], w1 = p2[2 * i + 1];
            #pragma unroll
            for (int c = 0; c < 8; c++) vr[c] = (vr[c] + bia + w0 * ppx[c] + w1 * ppy[c]) * bvc[c];
            float* o = g_imf + (size_t)b * CH * NP + (size_t)i * NP + j;
            *(float4*)o = make_float4(vr[0], vr[1], vr[2], vr[3]);
            *(float4*)(o + 4) = make_float4(vr[4], vr[5], vr[6], vr[7]);
        } else if constexpr (MODE == 2) {
            float w = g_wv[b * NP + i];
            #pragma unroll
            for (int c = 0; c < 8; c++) vr[c] *= w;
            float* o = g_xcat + ((size_t)(b * NP + i)) * (2 * CH) + CH + j;
            *(float4*)o = make_float4(vr[0], vr[1], vr[2], vr[3]);
            *(float4*)(o + 4) = make_float4(vr[4], vr[5], vr[6], vr[7]);
        } else if constexpr (MODE == 3) {
            #pragma unroll
            for (int c = 0; c < 8; c++) vr[c] += bc[c];
            float* o = g_x + ((size_t)(b * NP + i)) * CH + j;
            *(float4*)o = make_float4(vr[0], vr[1], vr[2], vr[3]);
            *(float4*)(o + 4) = make_float4(vr[4], vr[5], vr[6], vr[7]);
        } else if constexpr (MODE == 4) {
            #pragma unroll
            for (int c = 0; c < 8; c++) vr[c] = fmaxf(vr[c] + bc[c], 0.f);
            float* o = g_h + ((size_t)(b * NP + i)) * FFNC + j;
            *(float4*)o = make_float4(vr[0], vr[1], vr[2], vr[3]);
            *(float4*)(o + 4) = make_float4(vr[4], vr[5], vr[6], vr[7]);
        } else {
            const float* rsd = g_x + ((size_t)(b * NP + i)) * CH + j;
            float4 r0 = *(const float4*)rsd, r1 = *(const float4*)(rsd + 4);
            vr[0] += bc[0] + r0.x; vr[1] += bc[1] + r0.y; vr[2] += bc[2] + r0.z; vr[3] += bc[3] + r0.w;
            vr[4] += bc[4] + r1.x; vr[5] += bc[5] + r1.y; vr[6] += bc[6] + r1.z; vr[7] += bc[7] + r1.w;
            float* o = g_y2 + ((size_t)(b * NP + i)) * CH + j;
            *(float4*)o = make_float4(vr[0], vr[1], vr[2], vr[3]);
            *(float4*)(o + 4) = make_float4(vr[4], vr[5], vr[6], vr[7]);
        }
    }
}

// ---------------- LayerNorm in place on g_x ----------------
__global__ void k_ln(const float* __restrict__ gamma, const float* __restrict__ beta) {
    int row = blockIdx.x * 8 + (threadIdx.x >> 5);
    int lane = threadIdx.x & 31;
    float* x = g_x + (size_t)row * CH + lane * 8;
    float4 v0 = *(float4*)x;
    float4 v1 = *(float4*)(x + 4);
    float s = v0.x + v0.y + v0.z + v0.w + v1.x + v1.y + v1.z + v1.w;
    float s2 = v0.x * v0.x + v0.y * v0.y + v0.z * v0.z + v0.w * v0.w +
               v1.x * v1.x + v1.y * v1.y + v1.z * v1.z + v1.w * v1.w;
    #pragma unroll
    for (int o = 16; o; o >>= 1) {
        s  += __shfl_xor_sync(0xffffffffu, s, o);
        s2 += __shfl_xor_sync(0xffffffffu, s2, o);
    }
    float mu = s * (1.f / CH);
    float var = s2 * (1.f / CH) - mu * mu;
    float inv = rsqrtf(var + 1e-5f);
    int c = lane * 8;
    float4 g0 = *(const float4*)(gamma + c), g1 = *(const float4*)(gamma + c + 4);
    float4 b0 = *(const float4*)(beta + c),  b1 = *(const float4*)(beta + c + 4);
    v0.x = (v0.x - mu) * inv * g0.x + b0.x; v0.y = (v0.y - mu) * inv * g0.y + b0.y;
    v0.z = (v0.z - mu) * inv * g0.z + b0.z; v0.w = (v0.w - mu) * inv * g0.w + b0.w;
    v1.x = (v1.x - mu) * inv * g1.x + b1.x; v1.y = (v1.y - mu) * inv * g1.y + b1.y;
    v1.z = (v1.z - mu) * inv * g1.z + b1.z; v1.w = (v1.w - mu) * inv * g1.w + b1.w;
    *(float4*)x = v0;
    *(float4*)(x + 4) = v1;
}

// ---------------- final LN + prediction head + outputs ----------------
__global__ void k_final(const float* __restrict__ gamma, const float* __restrict__ beta,
                        const float* __restrict__ Wpred, const float* __restrict__ bpred,
                        const float* __restrict__ ppos,
                        float* __restrict__ out_x, float* __restrict__ out_np,
                        float* __restrict__ out_c) {
    int row = blockIdx.x * 8 + (threadIdx.x >> 5);
    int lane = threadIdx.x & 31;
    int b = row >> 11, n = row & (NP - 1);
    const float* y = g_y2 + (size_t)row * CH + lane * 8;
    float4 v0 = *(const float4*)y;
    float4 v1 = *(const float4*)(y + 4);
    float s = v0.x + v0.y + v0.z + v0.w + v1.x + v1.y + v1.z + v1.w;
    float s2 = v0.x * v0.x + v0.y * v0.y + v0.z * v0.z + v0.w * v0.w +
               v1.x * v1.x + v1.y * v1.y + v1.z * v1.z + v1.w * v1.w;
    #pragma unroll
    for (int o = 16; o; o >>= 1) {
        s  += __shfl_xor_sync(0xffffffffu, s, o);
        s2 += __shfl_xor_sync(0xffffffffu, s2, o);
    }
    float mu = s * (1.f / CH);
    float var = s2 * (1.f / CH) - mu * mu;
    float inv = rsqrtf(var + 1e-5f);
    int c = lane * 8;
    float4 g0 = *(const float4*)(gamma + c), g1 = *(const float4*)(gamma + c + 4);
    float4 b0 = *(const float4*)(beta + c),  b1 = *(const float4*)(beta + c + 4);
    v0.x = (v0.x - mu) * inv * g0.x + b0.x; v0.y = (v0.y - mu) * inv * g0.y + b0.y;
    v0.z = (v0.z - mu) * inv * g0.z + b0.z; v0.w = (v0.w - mu) * inv * g0.w + b0.w;
    v1.x = (v1.x - mu) * inv * g1.x + b1.x; v1.y = (v1.y - mu) * inv * g1.y + b1.y;
    v1.z = (v1.z - mu) * inv * g1.z + b1.z; v1.w = (v1.w - mu) * inv * g1.w + b1.w;

    float4 w00 = *(const float4*)(Wpred + c),      w01 = *(const float4*)(Wpred + c + 4);
    float4 w10 = *(const float4*)(Wpred + CH + c), w11 = *(const float4*)(Wpred + CH + c + 4);
    float d0 = v0.x * w00.x + v0.y * w00.y + v0.z * w00.z + v0.w * w00.w +
               v1.x * w01.x + v1.y * w01.y + v1.z * w01.z + v1.w * w01.w;
    float d1 = v0.x * w10.x + v0.y * w10.y + v0.z * w10.z + v0.w * w10.w +
               v1.x * w11.x + v1.y * w11.y + v1.z * w11.z + v1.w * w11.w;
    #pragma unroll
    for (int o = 16; o; o >>= 1) {
        d0 += __shfl_xor_sync(0xffffffffu, d0, o);
        d1 += __shfl_xor_sync(0xffffffffu, d1, o);
    }
    float* ox = out_x + (size_t)b * CH * NP + n;
    ox[(size_t)(c + 0) * NP] = v0.x; ox[(size_t)(c + 1) * NP] = v0.y;
    ox[(size_t)(c + 2) * NP] = v0.z; ox[(size_t)(c + 3) * NP] = v0.w;
    ox[(size_t)(c + 4) * NP] = v1.x; ox[(size_t)(c + 5) * NP] = v1.y;
    ox[(size_t)(c + 6) * NP] = v1.z; ox[(size_t)(c + 7) * NP] = v1.w;
    if (lane == 0) {
        float2 pp = ((const float2*)ppos)[b * NP + n];
        float c0 = d0 + bpred[0] + pp.x;
        float c1 = d1 + bpred[1] + pp.y;
        out_c[(size_t)b * 2 * NP + n] = c0;
        out_c[(size_t)b * 2 * NP + NP + n] = c1;
        ((float2*)out_np)[b * NP + n] = make_float2(c0, c1);
    }
}

// ---------------- launch ----------------
extern "C" void kernel_launch(void* const* d_in, const int* in_sizes, int n_in,
                              void* d_out, int out_size) {
    const float* ptsf   = (const float*)d_in[0];
    const float* ppos   = (const float*)d_in[1];
    const float* imgf   = (const float*)d_in[2];
    const float* ipos   = (const float*)d_in[3];
    const float* ptscls = (const float*)d_in[4];
    const float* imgcls = (const float*)d_in[5];
    const float* Wp  = (const float*)d_in[6];  const float* bp  = (const float*)d_in[7];
    const float* Wi  = (const float*)d_in[8];  const float* bi  = (const float*)d_in[9];
    const float* Wqp = (const float*)d_in[10]; const float* bqp = (const float*)d_in[11];
    const float* Wkp = (const float*)d_in[12]; const float* bkp = (const float*)d_in[13];
    const float* Wout = (const float*)d_in[14]; const float* bout = (const float*)d_in[15];
    const float* gout = (const float*)d_in[16]; const float* betaout = (const float*)d_in[17];
    const float* Wf1 = (const float*)d_in[18]; const float* bf1 = (const float*)d_in[19];
    const float* Wf2 = (const float*)d_in[20]; const float* bf2 = (const float*)d_in[21];
    const float* gln = (const float*)d_in[22]; const float* bln = (const float*)d_in[23];
    const float* Wpred = (const float*)d_in[24]; const float* bpred = (const float*)d_in[25];

    float* out    = (float*)d_out;
    float* out_x  = out;                                   // [2,256,2048]
    float* out_np = out + (size_t)BSZ * CH * NP;           // [2,2048,2]
    float* out_c  = out_np + (size_t)BSZ * NP * 2;         // [2,2,2048]

    dim3 tb(32, 8);
    k_cls<<<NROW / 256, 256>>>(ptscls, imgcls);                    // launch 1
    k_transpose<<<dim3(NP / 32, CH / 32, BSZ), tb>>>(ptsf, 0);     // launch 2
    k_transpose<<<dim3(NP / 32, CH / 32, BSZ), tb>>>(imgf, 1);     // launch 3

    // launch 4 (ncu capture slot): ALL 100 IPOT iterations + b_final + rownorm
    k_ipot_persist<<<NBLK, 256>>>(ppos, ipos);

    // projections + positional embeddings
    k_gemm<0><<<dim3(CH / 128, NP / 128, BSZ), 256>>>(Wp, bp, bqp, Wqp, ppos);
    k_gemm<1><<<dim3(NP / 128, CH / 128, BSZ), 256>>>(Wi, bi, bkp, Wkp, ipos);  // *bv folded

    // attention GEMM: img_att = w ⊙ (Q_fp16 @ imf_scaled^T)
    k_gemm<2><<<dim3(CH / 128, NP / 128, BSZ), 256>>>(nullptr, nullptr, nullptr, nullptr, nullptr);
    // out projection + LN
    k_gemm<3><<<dim3(CH / 128, NP / 128, BSZ), 256>>>(Wout, bout, nullptr, nullptr, nullptr);
    k_ln<<<NROW / 8, 256>>>(gout, betaout);
    // FFN
    k_gemm<4><<<dim3(FFNC / 128, NP / 128, BSZ), 256>>>(Wf1, bf1, nullptr, nullptr, nullptr);
    k_gemm<5><<<dim3(CH / 128, NP / 128, BSZ), 256>>>(Wf2, bf2, nullptr, nullptr, nullptr);
    // final LN + head + outputs
    k_final<<<NROW / 8, 256>>>(gln, bln, Wpred, bpred, ppos, out_x, out_np, out_c);
}

// round 8
// speedup vs baseline: 1.5491x; 1.5491x over previous
#include <cuda_runtime.h>
#include <cuda_fp16.h>
#include <math.h>

#define BSZ 2
#define NP  2048
#define CH  256
#define FFNC 1024
#define NROW (BSZ*NP)
#define NBLK 256           // persistent IPOT grid (128 per batch, 16 rows each)

// ---------------- scratch (device globals; no allocations) ----------------
__device__ __half g_Qh[(size_t)BSZ*NP*NP];   // IPOT transport matrix (fp16), in place
__device__ __half g_Gh[(size_t)BSZ*NP*NP];   // exp(-cost/10) (fp16)
__device__ float g_Xtp[(size_t)BSZ*NP*CH];   // pts feat transposed [b,n,c]
__device__ float g_Xti[(size_t)BSZ*NP*CH];   // img feat transposed [b,n,c]
__device__ float g_imf[(size_t)BSZ*CH*NP];   // img projected feat [b,c,m] (pre-scaled by b)
__device__ float g_xcat[(size_t)BSZ*NP*2*CH];// [pf ; img_att] token-major [b,n,512]
__device__ float g_x[(size_t)BSZ*NP*CH];     // post out-proj (+LN in place)
__device__ float g_h[(size_t)BSZ*NP*FFNC];   // FFN hidden
__device__ float g_y2[(size_t)BSZ*NP*CH];    // FFN out + residual
__device__ float g_pcls[NROW], g_icls[NROW];
__device__ float g_bv[NROW], g_wv[NROW];
__device__ float g_v[3][NROW];               // triple-buffered column sums v = Q^T a

// grid-barrier state (zero-initialized; g_gen monotonic across replays)
__device__ unsigned g_cnt8[8];
__device__ unsigned g_cntm;
__device__ volatile unsigned g_gen;

// ---------------- software grid barrier (all NBLK CTAs co-resident) ----------------
__device__ __forceinline__ void gridbar() {
    __syncthreads();
    if (threadIdx.x == 0) {
        unsigned my = g_gen;
        __threadfence();
        unsigned s = blockIdx.x & 7;                 // 8 groups of 32
        if (atomicAdd(&g_cnt8[s], 1) == 31) {
            g_cnt8[s] = 0;
            if (atomicAdd(&g_cntm, 1) == 7) {
                g_cntm = 0;
                __threadfence();
                g_gen = my + 1;
            }
        }
        while (g_gen == my) { __nanosleep(64); }
        __threadfence();
    }
    __syncthreads();
}

// ---------------- transpose [b,C,N] -> [b,N,C] ----------------
__global__ void k_transpose(const float* __restrict__ src, int which) {
    __shared__ float t[32][33];
    int b = blockIdx.z;
    float* dst = which ? g_Xti : g_Xtp;
    const float* s = src + (size_t)b * CH * NP;
    float* d = dst + (size_t)b * NP * CH;
    int n0 = blockIdx.x * 32, c0 = blockIdx.y * 32;
    for (int i = threadIdx.y; i < 32; i += 8)
        t[i][threadIdx.x] = s[(size_t)(c0 + i) * NP + n0 + threadIdx.x];
    __syncthreads();
    for (int i = threadIdx.y; i < 32; i += 8)
        d[(size_t)(n0 + i) * CH + c0 + threadIdx.x] = t[threadIdx.x][i];
}

// ---------------- pcls/icls = sigmoid(max over classes) ----------------
__global__ void k_cls(const float* __restrict__ pc, const float* __restrict__ ic) {
    int idx = blockIdx.x * 256 + threadIdx.x;   // 0..4095
    int b = idx >> 11, n = idx & (NP - 1);
    const float* p = pc + (size_t)b * 10 * NP + n;
    const float* q = ic + (size_t)b * 10 * NP + n;
    float mp = -1e30f, mi = -1e30f;
    #pragma unroll
    for (int c = 0; c < 10; c++) {
        mp = fmaxf(mp, p[(size_t)c * NP]);
        mi = fmaxf(mi, q[(size_t)c * NP]);
    }
    g_pcls[idx] = 1.f / (1.f + expf(-mp));
    g_icls[idx] = 1.f / (1.f + expf(-mi));
}

// ---------------- persistent IPOT: all 100 iterations in one kernel ----------------
// (R5 structure: warp-per-row, no syncs in the row loop, per-warp smem slots)
__global__ void __launch_bounds__(256, 2) k_ipot_persist(
    const float* __restrict__ ppos, const float* __restrict__ ipos) {
    extern __shared__ float sm[];         // 9*NP floats = 72KB
    float* sh_b = sm;
    float* sh_p = sm + NP;
    int tid = threadIdx.x, lane = tid & 31, wid = tid >> 5;
    int bid = blockIdx.x;
    int batch = bid >> 7, lb = bid & 127;
    int boff = batch * NP;
    int row0 = lb * 16;

    float pc0 = g_pcls[boff + row0 + wid];
    float pc1 = g_pcls[boff + row0 + wid + 8];
    float an_keep[2];
    an_keep[0] = 0.f; an_keep[1] = 0.f;

    // prologue: zero v[1] (t=1 accumulation target); idempotent across blocks
    #pragma unroll
    for (int j = 0; j < 8; j++) g_v[1][boff + tid + 256 * j] = 0.f;
    gridbar();

    for (int t = 1; t <= 100; t++) {
        // b into smem (t>1); zero v[(t+1)%3]
        {
            float* vz = g_v[(t + 1) % 3] + boff;
            if (t == 1) {
                #pragma unroll
                for (int j = 0; j < 8; j++) vz[tid + 256 * j] = 0.f;
            } else {
                const float* vr = g_v[(t - 1) % 3] + boff;
                const float* ic = g_icls + boff;
                #pragma unroll
                for (int j = 0; j < 8; j++) {
                    int m = tid + 256 * j;
                    sh_b[m] = __fdividef(ic[m], __ldcg(vr + m) + 1e-6f);
                    vz[m] = 0.f;
                }
            }
        }
        __syncthreads();

        float* pw = sh_p + wid * NP;
        #pragma unroll
        for (int rr = 0; rr < 2; rr++) {
            int row = row0 + wid + rr * 8;
            size_t base = (size_t)(boff + row) * NP;
            float qv[8][8];
            float u = 0.f;

            if (t == 1) {
                float2 pp = ((const float2*)ppos)[boff + row];
                const float2* ip = (const float2*)ipos + boff;
                #pragma unroll
                for (int j = 0; j < 8; j++) {
                    int c = (j * 32 + lane) * 8;
                    float qn[8];
                    #pragma unroll
                    for (int h = 0; h < 8; h++) {
                        float2 q2 = ip[c + h];
                        float dx = pp.x - q2.x, dy = pp.y - q2.y;
                        qn[h] = expf(-0.1f * sqrtf(dx * dx + dy * dy));
                    }
                    uint4 go; __half2* goh = (__half2*)&go;
                    uint4 qo; __half2* qoh = (__half2*)&qo;
                    #pragma unroll
                    for (int h = 0; h < 4; h++) {
                        goh[h] = __floats2half2_rn(qn[2 * h], qn[2 * h + 1]);
                        float a0 = fmaxf(qn[2 * h], 1e-6f), a1 = fmaxf(qn[2 * h + 1], 1e-6f);
                        qoh[h] = __floats2half2_rn(a0, a1);
                        qv[j][2 * h] = a0; qv[j][2 * h + 1] = a1;
                        u += a0 + a1;
                    }
                    *(uint4*)(g_Gh + base + c) = go;
                    *(uint4*)(g_Qh + base + c) = qo;
                }
                u *= (1.0f / NP);
            } else {
                float ap = an_keep[rr];
                #pragma unroll
                for (int j = 0; j < 8; j++) {
                    int c = (j * 32 + lane) * 8;
                    uint4 gq = *(const uint4*)(g_Gh + base + c);
                    uint4 qq = *(const uint4*)(g_Qh + base + c);
                    const __half2* gh = (const __half2*)&gq;
                    const __half2* qh = (const __half2*)&qq;
                    float4 b0 = *(const float4*)(sh_b + c);
                    float4 b1 = *(const float4*)(sh_b + c + 4);
                    float bb[8] = {b0.x, b0.y, b0.z, b0.w, b1.x, b1.y, b1.z, b1.w};
                    uint4 qo; __half2* qoh = (__half2*)&qo;
                    #pragma unroll
                    for (int h = 0; h < 4; h++) {
                        float2 gf = __half22float2(gh[h]);
                        float2 qf = __half22float2(qh[h]);
                        float n0 = fmaxf(gf.x * (ap * qf.x * bb[2 * h]), 1e-6f);
                        float n1 = fmaxf(gf.y * (ap * qf.y * bb[2 * h + 1]), 1e-6f);
                        qoh[h] = __floats2half2_rn(n0, n1);
                        qv[j][2 * h] = n0; qv[j][2 * h + 1] = n1;
                        u += n0 * bb[2 * h] + n1 * bb[2 * h + 1];
                    }
                    *(uint4*)(g_Qh + base + c) = qo;
                }
            }
            #pragma unroll
            for (int o = 16; o; o >>= 1) u += __shfl_xor_sync(0xffffffffu, u, o);
            float an = __fdividef((rr == 0 ? pc0 : pc1), u + 1e-6f);
            an_keep[rr] = an;

            if (rr == 0) {
                #pragma unroll
                for (int j = 0; j < 8; j++) {
                    int c = (j * 32 + lane) * 8;
                    #pragma unroll
                    for (int h = 0; h < 8; h++) pw[c + h] = an * qv[j][h];
                }
            } else {
                #pragma unroll
                for (int j = 0; j < 8; j++) {
                    int c = (j * 32 + lane) * 8;
                    #pragma unroll
                    for (int h = 0; h < 8; h++) pw[c + h] += an * qv[j][h];
                }
            }
        }
        __syncthreads();

        // combine 8 warp slots, flush once per block
        float* vw = g_v[t % 3] + boff;
        #pragma unroll
        for (int j = 0; j < 8; j++) {
            int m = tid + 256 * j;
            float s = 0.f;
            #pragma unroll
            for (int w = 0; w < 8; w++) s += sh_p[w * NP + m];
            atomicAdd(vw + m, s);
        }
        gridbar();
    }

    // epilogue: b_final = icls/(v[1]+eps) -> smem (+ g_bv once per batch)
    {
        const float* vf = g_v[1] + boff;
        const float* ic = g_icls + boff;
        #pragma unroll
        for (int j = 0; j < 8; j++) {
            int m = tid + 256 * j;
            float bf = __fdividef(ic[m], __ldcg(vf + m) + 1e-6f);
            sh_b[m] = bf;
            if (lb == 0) g_bv[boff + m] = bf;
        }
    }
    __syncthreads();

    // row-normalization scale w = a / max(a * rowsum(Q*b_final), 1e-12)
    #pragma unroll
    for (int rr = 0; rr < 2; rr++) {
        int row = row0 + wid + rr * 8;
        size_t base = (size_t)(boff + row) * NP;
        float srs = 0.f;
        #pragma unroll
        for (int j = 0; j < 8; j++) {
            int c = (j * 32 + lane) * 8;
            uint4 qq = *(const uint4*)(g_Qh + base + c);
            const __half2* qh = (const __half2*)&qq;
            float4 b0 = *(const float4*)(sh_b + c);
            float4 b1 = *(const float4*)(sh_b + c + 4);
            float bb[8] = {b0.x, b0.y, b0.z, b0.w, b1.x, b1.y, b1.z, b1.w};
            #pragma unroll
            for (int h = 0; h < 4; h++) {
                float2 qf = __half22float2(qh[h]);
                srs += qf.x * bb[2 * h] + qf.y * bb[2 * h + 1];
            }
        }
        #pragma unroll
        for (int o = 16; o; o >>= 1) srs += __shfl_xor_sync(0xffffffffu, srs, o);
        if (lane == 0) {
            float a = an_keep[rr];
            g_wv[boff + row] = a / fmaxf(a * srs, 1e-12f);
        }
    }
}

// ---------------- tiled GEMM 64x128x32, 4x8/thread: C[i,j] = sum_k A[i,k]*B[j,k] ----------------
// BM=64 doubles block count vs 128x128 (64 -> 128 blocks), fixing 43% SM coverage.
// MODE 0: pf   A=g_Xtp[b](2048x256)   B=Wp     -> xcat[:, :256] (+bp+bqp+Wqp·ppos(i))
// MODE 1: imf  A=Wi(256x256)          B=g_Xti  -> g_imf[b,c,m]  (+bi+bkp+Wkp·ipos(j)) * bv[j]
// MODE 2: att  A=g_Qh[b] (fp16)       B=g_imf  -> xcat[:,256:]  (*wv[i])
// MODE 3: proj A=g_xcat[b](2048x512)  B=Wout   -> g_x           (+bout)
// MODE 4: ffn1 A=g_x[b](2048x256)     B=Wf1    -> g_h           relu(+bf1)
// MODE 5: ffn2 A=g_h[b](2048x1024)    B=Wf2    -> g_y2          (+bf2 + g_x residual)
template<int MODE>
__global__ void __launch_bounds__(256) k_gemm(const float* __restrict__ e0,
                                              const float* __restrict__ p0,
                                              const float* __restrict__ p1,
                                              const float* __restrict__ p2,
                                              const float* __restrict__ p3) {
    constexpr int BM = 64, BN = 128, BK = 32;
    constexpr int K = (MODE == 0 || MODE == 1 || MODE == 4) ? 256 :
                      (MODE == 2 ? 2048 : (MODE == 3 ? 512 : 1024));
    int b = blockIdx.z;
    const float* A = nullptr; const float* Bm;
    if constexpr (MODE == 0)      { A = g_Xtp + (size_t)b * NP * CH;  Bm = e0; }
    else if constexpr (MODE == 1) { A = e0;                           Bm = g_Xti + (size_t)b * NP * CH; }
    else if constexpr (MODE == 2) { Bm = g_imf + (size_t)b * CH * NP; }
    else if constexpr (MODE == 3) { A = g_xcat + (size_t)b * NP * 2 * CH; Bm = e0; }
    else if constexpr (MODE == 4) { A = g_x + (size_t)b * NP * CH;    Bm = e0; }
    else                          { A = g_h + (size_t)b * NP * FFNC;  Bm = e0; }

    __shared__ float Asm[BK][BM + 4];
    __shared__ float Bsm[BK][BN + 4];
    int i0 = blockIdx.y * BM, j0 = blockIdx.x * BN;
    int tx = threadIdx.x & 15, ty = threadIdx.x >> 4;
    float acc[4][8];
    #pragma unroll
    for (int r = 0; r < 4; r++)
        #pragma unroll
        for (int c = 0; c < 8; c++) acc[r][c] = 0.f;

    for (int k0 = 0; k0 < K; k0 += BK) {
        if constexpr (MODE == 2) {
            const __half* Ah = g_Qh + (size_t)b * NP * NP;
            int f = threadIdx.x;
            int i = f >> 2, k8 = (f & 3) * 8;
            uint4 av = *(const uint4*)(Ah + (size_t)(i0 + i) * K + k0 + k8);
            const __half2* ah = (const __half2*)&av;
            #pragma unroll
            for (int h = 0; h < 4; h++) {
                float2 af = __half22float2(ah[h]);
                Asm[k8 + 2 * h][i] = af.x;
                Asm[k8 + 2 * h + 1][i] = af.y;
            }
        } else {
            #pragma unroll
            for (int s = 0; s < 2; s++) {
                int f4 = threadIdx.x + s * 256;
                int i = f4 >> 3, k4 = f4 & 7;
                float4 v = *(const float4*)(A + (size_t)(i0 + i) * K + k0 + k4 * 4);
                Asm[k4 * 4 + 0][i] = v.x; Asm[k4 * 4 + 1][i] = v.y;
                Asm[k4 * 4 + 2][i] = v.z; Asm[k4 * 4 + 3][i] = v.w;
            }
        }
        #pragma unroll
        for (int s = 0; s < 4; s++) {
            int f4 = threadIdx.x + s * 256;
            int j = f4 >> 3, k4 = f4 & 7;
            float4 v = *(const float4*)(Bm + (size_t)(j0 + j) * K + k0 + k4 * 4);
            Bsm[k4 * 4 + 0][j] = v.x; Bsm[k4 * 4 + 1][j] = v.y;
            Bsm[k4 * 4 + 2][j] = v.z; Bsm[k4 * 4 + 3][j] = v.w;
        }
        __syncthreads();
        #pragma unroll
        for (int kk = 0; kk < BK; kk++) {
            float4 a0 = *(const float4*)&Asm[kk][ty * 4];
            float4 b0 = *(const float4*)&Bsm[kk][tx * 8];
            float4 b1 = *(const float4*)&Bsm[kk][tx * 8 + 4];
            float ar[4] = {a0.x, a0.y, a0.z, a0.w};
            float br[8] = {b0.x, b0.y, b0.z, b0.w, b1.x, b1.y, b1.z, b1.w};
            #pragma unroll
            for (int r = 0; r < 4; r++)
                #pragma unroll
                for (int c = 0; c < 8; c++) acc[r][c] += ar[r] * br[c];
        }
        __syncthreads();
    }

    int j = j0 + tx * 8;
    float bc[8], w0c[8], w1c[8], ppx[8], ppy[8], bvc[8];
    if constexpr (MODE == 0) {
        #pragma unroll
        for (int c = 0; c < 8; c++) {
            bc[c] = p0[j + c] + p1[j + c];
            w0c[c] = p2[2 * (j + c)];
            w1c[c] = p2[2 * (j + c) + 1];
        }
    } else if constexpr (MODE == 1) {
        #pragma unroll
        for (int c = 0; c < 8; c++) {
            float2 pp = ((const float2*)p3)[b * NP + j + c];
            ppx[c] = pp.x; ppy[c] = pp.y;
            bvc[c] = g_bv[b * NP + j + c];
        }
    } else if constexpr (MODE == 3 || MODE == 4 || MODE == 5) {
        #pragma unroll
        for (int c = 0; c < 8; c++) bc[c] = p0[j + c];
    }

    #pragma unroll
    for (int r = 0; r < 4; r++) {
        int i = i0 + ty * 4 + r;
        float vr[8];
        #pragma unroll
        for (int c = 0; c < 8; c++) vr[c] = acc[r][c];
        if constexpr (MODE == 0) {
            float2 pp = ((const float2*)p3)[b * NP + i];
            #pragma unroll
            for (int c = 0; c < 8; c++) vr[c] += bc[c] + w0c[c] * pp.x + w1c[c] * pp.y;
            float* o = g_xcat + ((size_t)(b * NP + i)) * (2 * CH) + j;
            *(float4*)o = make_float4(vr[0], vr[1], vr[2], vr[3]);
            *(float4*)(o + 4) = make_float4(vr[4], vr[5], vr[6], vr[7]);
        } else if constexpr (MODE == 1) {
            float bia = p0[i] + p1[i];
            float w0 = p2[2 * i], w1 = p2[2 * i + 1];
            #pragma unroll
            for (int c = 0; c < 8; c++) vr[c] = (vr[c] + bia + w0 * ppx[c] + w1 * ppy[c]) * bvc[c];
            float* o = g_imf + (size_t)b * CH * NP + (size_t)i * NP + j;
            *(float4*)o = make_float4(vr[0], vr[1], vr[2], vr[3]);
            *(float4*)(o + 4) = make_float4(vr[4], vr[5], vr[6], vr[7]);
        } else if constexpr (MODE == 2) {
            float w = g_wv[b * NP + i];
            #pragma unroll
            for (int c = 0; c < 8; c++) vr[c] *= w;
            float* o = g_xcat + ((size_t)(b * NP + i)) * (2 * CH) + CH + j;
            *(float4*)o = make_float4(vr[0], vr[1], vr[2], vr[3]);
            *(float4*)(o + 4) = make_float4(vr[4], vr[5], vr[6], vr[7]);
        } else if constexpr (MODE == 3) {
            #pragma unroll
            for (int c = 0; c < 8; c++) vr[c] += bc[c];
            float* o = g_x + ((size_t)(b * NP + i)) * CH + j;
            *(float4*)o = make_float4(vr[0], vr[1], vr[2], vr[3]);
            *(float4*)(o + 4) = make_float4(vr[4], vr[5], vr[6], vr[7]);
        } else if constexpr (MODE == 4) {
            #pragma unroll
            for (int c = 0; c < 8; c++) vr[c] = fmaxf(vr[c] + bc[c], 0.f);
            float* o = g_h + ((size_t)(b * NP + i)) * FFNC + j;
            *(float4*)o = make_float4(vr[0], vr[1], vr[2], vr[3]);
            *(float4*)(o + 4) = make_float4(vr[4], vr[5], vr[6], vr[7]);
        } else {
            const float* rsd = g_x + ((size_t)(b * NP + i)) * CH + j;
            float4 r0 = *(const float4*)rsd, r1 = *(const float4*)(rsd + 4);
            vr[0] += bc[0] + r0.x; vr[1] += bc[1] + r0.y; vr[2] += bc[2] + r0.z; vr[3] += bc[3] + r0.w;
            vr[4] += bc[4] + r1.x; vr[5] += bc[5] + r1.y; vr[6] += bc[6] + r1.z; vr[7] += bc[7] + r1.w;
            float* o = g_y2 + ((size_t)(b * NP + i)) * CH + j;
            *(float4*)o = make_float4(vr[0], vr[1], vr[2], vr[3]);
            *(float4*)(o + 4) = make_float4(vr[4], vr[5], vr[6], vr[7]);
        }
    }
}

// ---------------- LayerNorm in place on g_x ----------------
__global__ void k_ln(const float* __restrict__ gamma, const float* __restrict__ beta) {
    int row = blockIdx.x * 8 + (threadIdx.x >> 5);
    int lane = threadIdx.x & 31;
    float* x = g_x + (size_t)row * CH + lane * 8;
    float4 v0 = *(float4*)x;
    float4 v1 = *(float4*)(x + 4);
    float s = v0.x + v0.y + v0.z + v0.w + v1.x + v1.y + v1.z + v1.w;
    float s2 = v0.x * v0.x + v0.y * v0.y + v0.z * v0.z + v0.w * v0.w +
               v1.x * v1.x + v1.y * v1.y + v1.z * v1.z + v1.w * v1.w;
    #pragma unroll
    for (int o = 16; o; o >>= 1) {
        s  += __shfl_xor_sync(0xffffffffu, s, o);
        s2 += __shfl_xor_sync(0xffffffffu, s2, o);
    }
    float mu = s * (1.f / CH);
    float var = s2 * (1.f / CH) - mu * mu;
    float inv = rsqrtf(var + 1e-5f);
    int c = lane * 8;
    float4 g0 = *(const float4*)(gamma + c), g1 = *(const float4*)(gamma + c + 4);
    float4 b0 = *(const float4*)(beta + c),  b1 = *(const float4*)(beta + c + 4);
    v0.x = (v0.x - mu) * inv * g0.x + b0.x; v0.y = (v0.y - mu) * inv * g0.y + b0.y;
    v0.z = (v0.z - mu) * inv * g0.z + b0.z; v0.w = (v0.w - mu) * inv * g0.w + b0.w;
    v1.x = (v1.x - mu) * inv * g1.x + b1.x; v1.y = (v1.y - mu) * inv * g1.y + b1.y;
    v1.z = (v1.z - mu) * inv * g1.z + b1.z; v1.w = (v1.w - mu) * inv * g1.w + b1.w;
    *(float4*)x = v0;
    *(float4*)(x + 4) = v1;
}

// ---------------- final LN + prediction head + outputs ----------------
__global__ void k_final(const float* __restrict__ gamma, const float* __restrict__ beta,
                        const float* __restrict__ Wpred, const float* __restrict__ bpred,
                        const float* __restrict__ ppos,
                        float* __restrict__ out_x, float* __restrict__ out_np,
                        float* __restrict__ out_c) {
    int row = blockIdx.x * 8 + (threadIdx.x >> 5);
    int lane = threadIdx.x & 31;
    int b = row >> 11, n = row & (NP - 1);
    const float* y = g_y2 + (size_t)row * CH + lane * 8;
    float4 v0 = *(const float4*)y;
    float4 v1 = *(const float4*)(y + 4);
    float s = v0.x + v0.y + v0.z + v0.w + v1.x + v1.y + v1.z + v1.w;
    float s2 = v0.x * v0.x + v0.y * v0.y + v0.z * v0.z + v0.w * v0.w +
               v1.x * v1.x + v1.y * v1.y + v1.z * v1.z + v1.w * v1.w;
    #pragma unroll
    for (int o = 16; o; o >>= 1) {
        s  += __shfl_xor_sync(0xffffffffu, s, o);
        s2 += __shfl_xor_sync(0xffffffffu, s2, o);
    }
    float mu = s * (1.f / CH);
    float var = s2 * (1.f / CH) - mu * mu;
    float inv = rsqrtf(var + 1e-5f);
    int c = lane * 8;
    float4 g0 = *(const float4*)(gamma + c), g1 = *(const float4*)(gamma + c + 4);
    float4 b0 = *(const float4*)(beta + c),  b1 = *(const float4*)(beta + c + 4);
    v0.x = (v0.x - mu) * inv * g0.x + b0.x; v0.y = (v0.y - mu) * inv * g0.y + b0.y;
    v0.z = (v0.z - mu) * inv * g0.z + b0.z; v0.w = (v0.w - mu) * inv * g0.w + b0.w;
    v1.x = (v1.x - mu) * inv * g1.x + b1.x; v1.y = (v1.y - mu) * inv * g1.y + b1.y;
    v1.z = (v1.z - mu) * inv * g1.z + b1.z; v1.w = (v1.w - mu) * inv * g1.w + b1.w;

    float4 w00 = *(const float4*)(Wpred + c),      w01 = *(const float4*)(Wpred + c + 4);
    float4 w10 = *(const float4*)(Wpred + CH + c), w11 = *(const float4*)(Wpred + CH + c + 4);
    float d0 = v0.x * w00.x + v0.y * w00.y + v0.z * w00.z + v0.w * w00.w +
               v1.x * w01.x + v1.y * w01.y + v1.z * w01.z + v1.w * w01.w;
    float d1 = v0.x * w10.x + v0.y * w10.y + v0.z * w10.z + v0.w * w10.w +
               v1.x * w11.x + v1.y * w11.y + v1.z * w11.z + v1.w * w11.w;
    #pragma unroll
    for (int o = 16; o; o >>= 1) {
        d0 += __shfl_xor_sync(0xffffffffu, d0, o);
        d1 += __shfl_xor_sync(0xffffffffu, d1, o);
    }
    float* ox = out_x + (size_t)b * CH * NP + n;
    ox[(size_t)(c + 0) * NP] = v0.x; ox[(size_t)(c + 1) * NP] = v0.y;
    ox[(size_t)(c + 2) * NP] = v0.z; ox[(size_t)(c + 3) * NP] = v0.w;
    ox[(size_t)(c + 4) * NP] = v1.x; ox[(size_t)(c + 5) * NP] = v1.y;
    ox[(size_t)(c + 6) * NP] = v1.z; ox[(size_t)(c + 7) * NP] = v1.w;
    if (lane == 0) {
        float2 pp = ((const float2*)ppos)[b * NP + n];
        float c0 = d0 + bpred[0] + pp.x;
        float c1 = d1 + bpred[1] + pp.y;
        out_c[(size_t)b * 2 * NP + n] = c0;
        out_c[(size_t)b * 2 * NP + NP + n] = c1;
        ((float2*)out_np)[b * NP + n] = make_float2(c0, c1);
    }
}

// ---------------- launch ----------------
extern "C" void kernel_launch(void* const* d_in, const int* in_sizes, int n_in,
                              void* d_out, int out_size) {
    const float* ptsf   = (const float*)d_in[0];
    const float* ppos   = (const float*)d_in[1];
    const float* imgf   = (const float*)d_in[2];
    const float* ipos   = (const float*)d_in[3];
    const float* ptscls = (const float*)d_in[4];
    const float* imgcls = (const float*)d_in[5];
    const float* Wp  = (const float*)d_in[6];  const float* bp  = (const float*)d_in[7];
    const float* Wi  = (const float*)d_in[8];  const float* bi  = (const float*)d_in[9];
    const float* Wqp = (const float*)d_in[10]; const float* bqp = (const float*)d_in[11];
    const float* Wkp = (const float*)d_in[12]; const float* bkp = (const float*)d_in[13];
    const float* Wout = (const float*)d_in[14]; const float* bout = (const float*)d_in[15];
    const float* gout = (const float*)d_in[16]; const float* betaout = (const float*)d_in[17];
    const float* Wf1 = (const float*)d_in[18]; const float* bf1 = (const float*)d_in[19];
    const float* Wf2 = (const float*)d_in[20]; const float* bf2 = (const float*)d_in[21];
    const float* gln = (const float*)d_in[22]; const float* bln = (const float*)d_in[23];
    const float* Wpred = (const float*)d_in[24]; const float* bpred = (const float*)d_in[25];

    float* out    = (float*)d_out;
    float* out_x  = out;                                   // [2,256,2048]
    float* out_np = out + (size_t)BSZ * CH * NP;           // [2,2048,2]
    float* out_c  = out_np + (size_t)BSZ * NP * 2;         // [2,2,2048]

    const int IPOT_SMEM = 9 * NP * (int)sizeof(float);     // 72 KB dynamic
    cudaFuncSetAttribute(k_ipot_persist, cudaFuncAttributeMaxDynamicSharedMemorySize, IPOT_SMEM);

    dim3 tb(32, 8);
    k_cls<<<NROW / 256, 256>>>(ptscls, imgcls);                    // launch 1
    k_transpose<<<dim3(NP / 32, CH / 32, BSZ), tb>>>(ptsf, 0);     // launch 2
    k_transpose<<<dim3(NP / 32, CH / 32, BSZ), tb>>>(imgf, 1);     // launch 3

    // launch 4 (ncu capture slot): ALL 100 IPOT iterations + b_final + rownorm
    k_ipot_persist<<<NBLK, 256, IPOT_SMEM>>>(ppos, ipos);

    // projections + positional embeddings
    k_gemm<0><<<dim3(CH / 128, NP / 64, BSZ), 256>>>(Wp, bp, bqp, Wqp, ppos);
    k_gemm<1><<<dim3(NP / 128, CH / 64, BSZ), 256>>>(Wi, bi, bkp, Wkp, ipos);  // *bv folded

    // attention GEMM: img_att = w ⊙ (Q_fp16 @ imf_scaled^T)
    k_gemm<2><<<dim3(CH / 128, NP / 64, BSZ), 256>>>(nullptr, nullptr, nullptr, nullptr, nullptr);
    // out projection + LN
    k_gemm<3><<<dim3(CH / 128, NP / 64, BSZ), 256>>>(Wout, bout, nullptr, nullptr, nullptr);
    k_ln<<<NROW / 8, 256>>>(gout, betaout);
    // FFN
    k_gemm<4><<<dim3(FFNC / 128, NP / 64, BSZ), 256>>>(Wf1, bf1, nullptr, nullptr, nullptr);
    k_gemm<5><<<dim3(CH / 128, NP / 64, BSZ), 256>>>(Wf2, bf2, nullptr, nullptr, nullptr);
    // final LN + head + outputs
    k_final<<<NROW / 8, 256>>>(gln, bln, Wpred, bpred, ppos, out_x, out_np, out_c);
}

// round 9
// speedup vs baseline: 1.6506x; 1.0655x over previous
#include <cuda_runtime.h>
#include <cuda_fp16.h>
#include <math.h>

#define BSZ 2
#define NP  2048
#define CH  256
#define FFNC 1024
#define NROW (BSZ*NP)
#define NBLK 256           // persistent IPOT grid (128 per batch, 16 rows each)

// ---------------- scratch (device globals; no allocations) ----------------
__device__ __half g_Qh[(size_t)BSZ*NP*NP];   // IPOT transport matrix (fp16), in place
__device__ __half g_Gh[(size_t)BSZ*NP*NP];   // exp(-cost/10) (fp16)
__device__ float g_Xtp[(size_t)BSZ*NP*CH];   // pts feat transposed [b,n,c]
__device__ float g_Xti[(size_t)BSZ*NP*CH];   // img feat transposed [b,n,c]
__device__ float g_imf[(size_t)BSZ*CH*NP];   // img projected feat [b,c,m] (pre-scaled by b)
__device__ float g_xcat[(size_t)BSZ*NP*2*CH];// [pf ; img_att] token-major [b,n,512]
__device__ float g_x[(size_t)BSZ*NP*CH];     // post out-proj (+LN in place)
__device__ float g_h[(size_t)BSZ*NP*FFNC];   // FFN hidden
__device__ float g_y2[(size_t)BSZ*NP*CH];    // FFN out + residual
__device__ float g_pcls[NROW], g_icls[NROW];
__device__ float g_bv[NROW], g_wv[NROW];
__device__ float g_v[3][NROW];               // triple-buffered column sums v = Q^T a

// grid-barrier state (zero-initialized; g_gen monotonic across replays)
__device__ unsigned g_cnt8[8];
__device__ unsigned g_cntm;
__device__ volatile unsigned g_gen;

// ---------------- software grid barrier (all NBLK CTAs co-resident) ----------------
__device__ __forceinline__ void gridbar() {
    __syncthreads();
    if (threadIdx.x == 0) {
        unsigned my = g_gen;
        __threadfence();
        unsigned s = blockIdx.x & 7;                 // 8 groups of 32
        if (atomicAdd(&g_cnt8[s], 1) == 31) {
            g_cnt8[s] = 0;
            if (atomicAdd(&g_cntm, 1) == 7) {
                g_cntm = 0;
                __threadfence();
                g_gen = my + 1;
            }
        }
        while (g_gen == my) { __nanosleep(32); }
        __threadfence();
    }
    __syncthreads();
}

// ---------------- transpose [b,C,N] -> [b,N,C] ----------------
__global__ void k_transpose(const float* __restrict__ src, int which) {
    __shared__ float t[32][33];
    int b = blockIdx.z;
    float* dst = which ? g_Xti : g_Xtp;
    const float* s = src + (size_t)b * CH * NP;
    float* d = dst + (size_t)b * NP * CH;
    int n0 = blockIdx.x * 32, c0 = blockIdx.y * 32;
    for (int i = threadIdx.y; i < 32; i += 8)
        t[i][threadIdx.x] = s[(size_t)(c0 + i) * NP + n0 + threadIdx.x];
    __syncthreads();
    for (int i = threadIdx.y; i < 32; i += 8)
        d[(size_t)(n0 + i) * CH + c0 + threadIdx.x] = t[threadIdx.x][i];
}

// ---------------- pcls/icls = sigmoid(max over classes) ----------------
__global__ void k_cls(const float* __restrict__ pc, const float* __restrict__ ic) {
    int idx = blockIdx.x * 256 + threadIdx.x;   // 0..4095
    int b = idx >> 11, n = idx & (NP - 1);
    const float* p = pc + (size_t)b * 10 * NP + n;
    const float* q = ic + (size_t)b * 10 * NP + n;
    float mp = -1e30f, mi = -1e30f;
    #pragma unroll
    for (int c = 0; c < 10; c++) {
        mp = fmaxf(mp, p[(size_t)c * NP]);
        mi = fmaxf(mi, q[(size_t)c * NP]);
    }
    g_pcls[idx] = 1.f / (1.f + expf(-mp));
    g_icls[idx] = 1.f / (1.f + expf(-mi));
}

// ---------------- persistent IPOT: all 100 iterations in one kernel ----------------
// R5 structure (warp-per-row, no syncs in row loop) with fp16 per-warp slots:
// deposit/RMW/combine all in half2, halving the dominant smem traffic.
__global__ void __launch_bounds__(256, 2) k_ipot_persist(
    const float* __restrict__ ppos, const float* __restrict__ ipos) {
    extern __shared__ float sm[];         // 8KB fp32 b + 32KB fp16 slots = 40KB
    float* sh_b = sm;
    __half* sh_ph = (__half*)(sm + NP);
    int tid = threadIdx.x, lane = tid & 31, wid = tid >> 5;
    int bid = blockIdx.x;
    int batch = bid >> 7, lb = bid & 127;
    int boff = batch * NP;
    int row0 = lb * 16;

    float pc0 = g_pcls[boff + row0 + wid];
    float pc1 = g_pcls[boff + row0 + wid + 8];
    float an_keep[2];
    an_keep[0] = 0.f; an_keep[1] = 0.f;

    // prologue: zero v[1] (t=1 accumulation target); idempotent across blocks
    #pragma unroll
    for (int j = 0; j < 8; j++) g_v[1][boff + tid + 256 * j] = 0.f;
    gridbar();

    for (int t = 1; t <= 100; t++) {
        // b into smem (t>1); zero v[(t+1)%3]
        {
            float* vz = g_v[(t + 1) % 3] + boff;
            if (t == 1) {
                #pragma unroll
                for (int j = 0; j < 8; j++) vz[tid + 256 * j] = 0.f;
            } else {
                const float* vr = g_v[(t - 1) % 3] + boff;
                const float* ic = g_icls + boff;
                #pragma unroll
                for (int j = 0; j < 8; j++) {
                    int m = tid + 256 * j;
                    sh_b[m] = __fdividef(ic[m], __ldcg(vr + m) + 1e-6f);
                    vz[m] = 0.f;
                }
            }
        }
        __syncthreads();

        __half* pwh = sh_ph + wid * NP;
        #pragma unroll
        for (int rr = 0; rr < 2; rr++) {
            int row = row0 + wid + rr * 8;
            size_t base = (size_t)(boff + row) * NP;
            float qv[8][8];
            float u = 0.f;

            if (t == 1) {
                float2 pp = ((const float2*)ppos)[boff + row];
                const float2* ip = (const float2*)ipos + boff;
                #pragma unroll
                for (int j = 0; j < 8; j++) {
                    int c = (j * 32 + lane) * 8;
                    float qn[8];
                    #pragma unroll
                    for (int h = 0; h < 8; h++) {
                        float2 q2 = ip[c + h];
                        float dx = pp.x - q2.x, dy = pp.y - q2.y;
                        qn[h] = expf(-0.1f * sqrtf(dx * dx + dy * dy));
                    }
                    uint4 go; __half2* goh = (__half2*)&go;
                    uint4 qo; __half2* qoh = (__half2*)&qo;
                    #pragma unroll
                    for (int h = 0; h < 4; h++) {
                        goh[h] = __floats2half2_rn(qn[2 * h], qn[2 * h + 1]);
                        float a0 = fmaxf(qn[2 * h], 1e-6f), a1 = fmaxf(qn[2 * h + 1], 1e-6f);
                        qoh[h] = __floats2half2_rn(a0, a1);
                        qv[j][2 * h] = a0; qv[j][2 * h + 1] = a1;
                        u += a0 + a1;
                    }
                    *(uint4*)(g_Gh + base + c) = go;
                    *(uint4*)(g_Qh + base + c) = qo;
                }
                u *= (1.0f / NP);
            } else {
                float ap = an_keep[rr];
                #pragma unroll
                for (int j = 0; j < 8; j++) {
                    int c = (j * 32 + lane) * 8;
                    uint4 gq = *(const uint4*)(g_Gh + base + c);
                    uint4 qq = *(const uint4*)(g_Qh + base + c);
                    const __half2* gh = (const __half2*)&gq;
                    const __half2* qh = (const __half2*)&qq;
                    float4 b0 = *(const float4*)(sh_b + c);
                    float4 b1 = *(const float4*)(sh_b + c + 4);
                    float bb[8] = {b0.x, b0.y, b0.z, b0.w, b1.x, b1.y, b1.z, b1.w};
                    uint4 qo; __half2* qoh = (__half2*)&qo;
                    #pragma unroll
                    for (int h = 0; h < 4; h++) {
                        float2 gf = __half22float2(gh[h]);
                        float2 qf = __half22float2(qh[h]);
                        float n0 = fmaxf(gf.x * (ap * qf.x * bb[2 * h]), 1e-6f);
                        float n1 = fmaxf(gf.y * (ap * qf.y * bb[2 * h + 1]), 1e-6f);
                        qoh[h] = __floats2half2_rn(n0, n1);
                        qv[j][2 * h] = n0; qv[j][2 * h + 1] = n1;
                        u += n0 * bb[2 * h] + n1 * bb[2 * h + 1];
                    }
                    *(uint4*)(g_Qh + base + c) = qo;
                }
            }
            #pragma unroll
            for (int o = 16; o; o >>= 1) u += __shfl_xor_sync(0xffffffffu, u, o);
            float an = __fdividef((rr == 0 ? pc0 : pc1), u + 1e-6f);
            an_keep[rr] = an;

            // deposit an*q into this warp's fp16 slot (overwrite rr=0, RMW rr=1)
            if (rr == 0) {
                #pragma unroll
                for (int j = 0; j < 8; j++) {
                    int c = (j * 32 + lane) * 8;
                    uint4 st; __half2* sth = (__half2*)&st;
                    #pragma unroll
                    for (int h = 0; h < 4; h++)
                        sth[h] = __floats2half2_rn(an * qv[j][2 * h], an * qv[j][2 * h + 1]);
                    *(uint4*)(pwh + c) = st;
                }
            } else {
                #pragma unroll
                for (int j = 0; j < 8; j++) {
                    int c = (j * 32 + lane) * 8;
                    uint4 old = *(uint4*)(pwh + c);
                    __half2* oh = (__half2*)&old;
                    uint4 st; __half2* sth = (__half2*)&st;
                    #pragma unroll
                    for (int h = 0; h < 4; h++) {
                        float2 f = __half22float2(oh[h]);
                        sth[h] = __floats2half2_rn(f.x + an * qv[j][2 * h],
                                                   f.y + an * qv[j][2 * h + 1]);
                    }
                    *(uint4*)(pwh + c) = st;
                }
            }
        }
        __syncthreads();

        // combine 8 warp slots (half2 pairs), flush once per block
        float* vw = g_v[t % 3] + boff;
        #pragma unroll
        for (int jj = 0; jj < 4; jj++) {
            int m = 2 * tid + 512 * jj;
            float s0 = 0.f, s1 = 0.f;
            #pragma unroll
            for (int w = 0; w < 8; w++) {
                __half2 hv = *(const __half2*)(sh_ph + w * NP + m);
                float2 f = __half22float2(hv);
                s0 += f.x; s1 += f.y;
            }
            atomicAdd(vw + m, s0);
            atomicAdd(vw + m + 1, s1);
        }
        gridbar();
    }

    // epilogue: b_final = icls/(v[1]+eps) -> smem (+ g_bv once per batch)
    {
        const float* vf = g_v[1] + boff;
        const float* ic = g_icls + boff;
        #pragma unroll
        for (int j = 0; j < 8; j++) {
            int m = tid + 256 * j;
            float bf = __fdividef(ic[m], __ldcg(vf + m) + 1e-6f);
            sh_b[m] = bf;
            if (lb == 0) g_bv[boff + m] = bf;
        }
    }
    __syncthreads();

    // row-normalization scale w = a / max(a * rowsum(Q*b_final), 1e-12)
    __shared__ float uwf[2][8];
    #pragma unroll
    for (int rr = 0; rr < 2; rr++) {
        int row = row0 + wid + rr * 8;
        size_t base = (size_t)(boff + row) * NP;
        float srs = 0.f;
        #pragma unroll
        for (int j = 0; j < 8; j++) {
            int c = (j * 32 + lane) * 8;
            uint4 qq = *(const uint4*)(g_Qh + base + c);
            const __half2* qh = (const __half2*)&qq;
            float4 b0 = *(const float4*)(sh_b + c);
            float4 b1 = *(const float4*)(sh_b + c + 4);
            float bb[8] = {b0.x, b0.y, b0.z, b0.w, b1.x, b1.y, b1.z, b1.w};
            #pragma unroll
            for (int h = 0; h < 4; h++) {
                float2 qf = __half22float2(qh[h]);
                srs += qf.x * bb[2 * h] + qf.y * bb[2 * h + 1];
            }
        }
        #pragma unroll
        for (int o = 16; o; o >>= 1) srs += __shfl_xor_sync(0xffffffffu, srs, o);
        if (lane == 0) {
            float a = an_keep[rr];
            g_wv[boff + row] = a / fmaxf(a * srs, 1e-12f);
        }
        (void)uwf;
    }
}

// ---------------- tiled GEMM 64x128x32, 4x8/thread: C[i,j] = sum_k A[i,k]*B[j,k] ----------------
// MODE 0: pf   A=g_Xtp[b](2048x256)   B=Wp     -> xcat[:, :256] (+bp+bqp+Wqp·ppos(i))
// MODE 1: imf  A=Wi(256x256)          B=g_Xti  -> g_imf[b,c,m]  (+bi+bkp+Wkp·ipos(j)) * bv[j]
// MODE 2: att  A=g_Qh[b] (fp16)       B=g_imf  -> xcat[:,256:]  (*wv[i])
// MODE 3: proj A=g_xcat[b](2048x512)  B=Wout   -> g_x           (+bout)
// MODE 4: ffn1 A=g_x[b](2048x256)     B=Wf1    -> g_h           relu(+bf1)
// MODE 5: ffn2 A=g_h[b](2048x1024)    B=Wf2    -> g_y2          (+bf2 + g_x residual)
template<int MODE>
__global__ void __launch_bounds__(256) k_gemm(const float* __restrict__ e0,
                                              const float* __restrict__ p0,
                                              const float* __restrict__ p1,
                                              const float* __restrict__ p2,
                                              const float* __restrict__ p3) {
    constexpr int BM = 64, BN = 128, BK = 32;
    constexpr int K = (MODE == 0 || MODE == 1 || MODE == 4) ? 256 :
                      (MODE == 2 ? 2048 : (MODE == 3 ? 512 : 1024));
    int b = blockIdx.z;
    const float* A = nullptr; const float* Bm;
    if constexpr (MODE == 0)      { A = g_Xtp + (size_t)b * NP * CH;  Bm = e0; }
    else if constexpr (MODE == 1) { A = e0;                           Bm = g_Xti + (size_t)b * NP * CH; }
    else if constexpr (MODE == 2) { Bm = g_imf + (size_t)b * CH * NP; }
    else if constexpr (MODE == 3) { A = g_xcat + (size_t)b * NP * 2 * CH; Bm = e0; }
    else if constexpr (MODE == 4) { A = g_x + (size_t)b * NP * CH;    Bm = e0; }
    else                          { A = g_h + (size_t)b * NP * FFNC;  Bm = e0; }

    __shared__ float Asm[BK][BM + 4];
    __shared__ float Bsm[BK][BN + 4];
    int i0 = blockIdx.y * BM, j0 = blockIdx.x * BN;
    int tx = threadIdx.x & 15, ty = threadIdx.x >> 4;
    float acc[4][8];
    #pragma unroll
    for (int r = 0; r < 4; r++)
        #pragma unroll
        for (int c = 0; c < 8; c++) acc[r][c] = 0.f;

    for (int k0 = 0; k0 < K; k0 += BK) {
        if constexpr (MODE == 2) {
            const __half* Ah = g_Qh + (size_t)b * NP * NP;
            int f = threadIdx.x;
            int i = f >> 2, k8 = (f & 3) * 8;
            uint4 av = *(const uint4*)(Ah + (size_t)(i0 + i) * K + k0 + k8);
            const __half2* ah = (const __half2*)&av;
            #pragma unroll
            for (int h = 0; h < 4; h++) {
                float2 af = __half22float2(ah[h]);
                Asm[k8 + 2 * h][i] = af.x;
                Asm[k8 + 2 * h + 1][i] = af.y;
            }
        } else {
            #pragma unroll
            for (int s = 0; s < 2; s++) {
                int f4 = threadIdx.x + s * 256;
                int i = f4 >> 3, k4 = f4 & 7;
                float4 v = *(const float4*)(A + (size_t)(i0 + i) * K + k0 + k4 * 4);
                Asm[k4 * 4 + 0][i] = v.x; Asm[k4 * 4 + 1][i] = v.y;
                Asm[k4 * 4 + 2][i] = v.z; Asm[k4 * 4 + 3][i] = v.w;
            }
        }
        #pragma unroll
        for (int s = 0; s < 4; s++) {
            int f4 = threadIdx.x + s * 256;
            int j = f4 >> 3, k4 = f4 & 7;
            float4 v = *(const float4*)(Bm + (size_t)(j0 + j) * K + k0 + k4 * 4);
            Bsm[k4 * 4 + 0][j] = v.x; Bsm[k4 * 4 + 1][j] = v.y;
            Bsm[k4 * 4 + 2][j] = v.z; Bsm[k4 * 4 + 3][j] = v.w;
        }
        __syncthreads();
        #pragma unroll
        for (int kk = 0; kk < BK; kk++) {
            float4 a0 = *(const float4*)&Asm[kk][ty * 4];
            float4 b0 = *(const float4*)&Bsm[kk][tx * 8];
            float4 b1 = *(const float4*)&Bsm[kk][tx * 8 + 4];
            float ar[4] = {a0.x, a0.y, a0.z, a0.w};
            float br[8] = {b0.x, b0.y, b0.z, b0.w, b1.x, b1.y, b1.z, b1.w};
            #pragma unroll
            for (int r = 0; r < 4; r++)
                #pragma unroll
                for (int c = 0; c < 8; c++) acc[r][c] += ar[r] * br[c];
        }
        __syncthreads();
    }

    int j = j0 + tx * 8;
    float bc[8], w0c[8], w1c[8], ppx[8], ppy[8], bvc[8];
    if constexpr (MODE == 0) {
        #pragma unroll
        for (int c = 0; c < 8; c++) {
            bc[c] = p0[j + c] + p1[j + c];
            w0c[c] = p2[2 * (j + c)];
            w1c[c] = p2[2 * (j + c) + 1];
        }
    } else if constexpr (MODE == 1) {
        #pragma unroll
        for (int c = 0; c < 8; c++) {
            float2 pp = ((const float2*)p3)[b * NP + j + c];
            ppx[c] = pp.x; ppy[c] = pp.y;
            bvc[c] = g_bv[b * NP + j + c];
        }
    } else if constexpr (MODE == 3 || MODE == 4 || MODE == 5) {
        #pragma unroll
        for (int c = 0; c < 8; c++) bc[c] = p0[j + c];
    }

    #pragma unroll
    for (int r = 0; r < 4; r++) {
        int i = i0 + ty * 4 + r;
        float vr[8];
        #pragma unroll
        for (int c = 0; c < 8; c++) vr[c] = acc[r][c];
        if constexpr (MODE == 0) {
            float2 pp = ((const float2*)p3)[b * NP + i];
            #pragma unroll
            for (int c = 0; c < 8; c++) vr[c] += bc[c] + w0c[c] * pp.x + w1c[c] * pp.y;
            float* o = g_xcat + ((size_t)(b * NP + i)) * (2 * CH) + j;
            *(float4*)o = make_float4(vr[0], vr[1], vr[2], vr[3]);
            *(float4*)(o + 4) = make_float4(vr[4], vr[5], vr[6], vr[7]);
        } else if constexpr (MODE == 1) {
            float bia = p0[i] + p1[i];
            float w0 = p2[2 * i], w1 = p2[2 * i + 1];
            #pragma unroll
            for (int c = 0; c < 8; c++) vr[c] = (vr[c] + bia + w0 * ppx[c] + w1 * ppy[c]) * bvc[c];
            float* o = g_imf + (size_t)b * CH * NP + (size_t)i * NP + j;
            *(float4*)o = make_float4(vr[0], vr[1], vr[2], vr[3]);
            *(float4*)(o + 4) = make_float4(vr[4], vr[5], vr[6], vr[7]);
        } else if constexpr (MODE == 2) {
            float w = g_wv[b * NP + i];
            #pragma unroll
            for (int c = 0; c < 8; c++) vr[c] *= w;
            float* o = g_xcat + ((size_t)(b * NP + i)) * (2 * CH) + CH + j;
            *(float4*)o = make_float4(vr[0], vr[1], vr[2], vr[3]);
            *(float4*)(o + 4) = make_float4(vr[4], vr[5], vr[6], vr[7]);
        } else if constexpr (MODE == 3) {
            #pragma unroll
            for (int c = 0; c < 8; c++) vr[c] += bc[c];
            float* o = g_x + ((size_t)(b * NP + i)) * CH + j;
            *(float4*)o = make_float4(vr[0], vr[1], vr[2], vr[3]);
            *(float4*)(o + 4) = make_float4(vr[4], vr[5], vr[6], vr[7]);
        } else if constexpr (MODE == 4) {
            #pragma unroll
            for (int c = 0; c < 8; c++) vr[c] = fmaxf(vr[c] + bc[c], 0.f);
            float* o = g_h + ((size_t)(b * NP + i)) * FFNC + j;
            *(float4*)o = make_float4(vr[0], vr[1], vr[2], vr[3]);
            *(float4*)(o + 4) = make_float4(vr[4], vr[5], vr[6], vr[7]);
        } else {
            const float* rsd = g_x + ((size_t)(b * NP + i)) * CH + j;
            float4 r0 = *(const float4*)rsd, r1 = *(const float4*)(rsd + 4);
            vr[0] += bc[0] + r0.x; vr[1] += bc[1] + r0.y; vr[2] += bc[2] + r0.z; vr[3] += bc[3] + r0.w;
            vr[4] += bc[4] + r1.x; vr[5] += bc[5] + r1.y; vr[6] += bc[6] + r1.z; vr[7] += bc[7] + r1.w;
            float* o = g_y2 + ((size_t)(b * NP + i)) * CH + j;
            *(float4*)o = make_float4(vr[0], vr[1], vr[2], vr[3]);
            *(float4*)(o + 4) = make_float4(vr[4], vr[5], vr[6], vr[7]);
        }
    }
}

// ---------------- LayerNorm in place on g_x ----------------
__global__ void k_ln(const float* __restrict__ gamma, const float* __restrict__ beta) {
    int row = blockIdx.x * 8 + (threadIdx.x >> 5);
    int lane = threadIdx.x & 31;
    float* x = g_x + (size_t)row * CH + lane * 8;
    float4 v0 = *(float4*)x;
    float4 v1 = *(float4*)(x + 4);
    float s = v0.x + v0.y + v0.z + v0.w + v1.x + v1.y + v1.z + v1.w;
    float s2 = v0.x * v0.x + v0.y * v0.y + v0.z * v0.z + v0.w * v0.w +
               v1.x * v1.x + v1.y * v1.y + v1.z * v1.z + v1.w * v1.w;
    #pragma unroll
    for (int o = 16; o; o >>= 1) {
        s  += __shfl_xor_sync(0xffffffffu, s, o);
        s2 += __shfl_xor_sync(0xffffffffu, s2, o);
    }
    float mu = s * (1.f / CH);
    float var = s2 * (1.f / CH) - mu * mu;
    float inv = rsqrtf(var + 1e-5f);
    int c = lane * 8;
    float4 g0 = *(const float4*)(gamma + c), g1 = *(const float4*)(gamma + c + 4);
    float4 b0 = *(const float4*)(beta + c),  b1 = *(const float4*)(beta + c + 4);
    v0.x = (v0.x - mu) * inv * g0.x + b0.x; v0.y = (v0.y - mu) * inv * g0.y + b0.y;
    v0.z = (v0.z - mu) * inv * g0.z + b0.z; v0.w = (v0.w - mu) * inv * g0.w + b0.w;
    v1.x = (v1.x - mu) * inv * g1.x + b1.x; v1.y = (v1.y - mu) * inv * g1.y + b1.y;
    v1.z = (v1.z - mu) * inv * g1.z + b1.z; v1.w = (v1.w - mu) * inv * g1.w + b1.w;
    *(float4*)x = v0;
    *(float4*)(x + 4) = v1;
}

// ---------------- final LN + prediction head + outputs ----------------
__global__ void k_final(const float* __restrict__ gamma, const float* __restrict__ beta,
                        const float* __restrict__ Wpred, const float* __restrict__ bpred,
                        const float* __restrict__ ppos,
                        float* __restrict__ out_x, float* __restrict__ out_np,
                        float* __restrict__ out_c) {
    int row = blockIdx.x * 8 + (threadIdx.x >> 5);
    int lane = threadIdx.x & 31;
    int b = row >> 11, n = row & (NP - 1);
    const float* y = g_y2 + (size_t)row * CH + lane * 8;
    float4 v0 = *(const float4*)y;
    float4 v1 = *(const float4*)(y + 4);
    float s = v0.x + v0.y + v0.z + v0.w + v1.x + v1.y + v1.z + v1.w;
    float s2 = v0.x * v0.x + v0.y * v0.y + v0.z * v0.z + v0.w * v0.w +
               v1.x * v1.x + v1.y * v1.y + v1.z * v1.z + v1.w * v1.w;
    #pragma unroll
    for (int o = 16; o; o >>= 1) {
        s  += __shfl_xor_sync(0xffffffffu, s, o);
        s2 += __shfl_xor_sync(0xffffffffu, s2, o);
    }
    float mu = s * (1.f / CH);
    float var = s2 * (1.f / CH) - mu * mu;
    float inv = rsqrtf(var + 1e-5f);
    int c = lane * 8;
    float4 g0 = *(const float4*)(gamma + c), g1 = *(const float4*)(gamma + c + 4);
    float4 b0 = *(const float4*)(beta + c),  b1 = *(const float4*)(beta + c + 4);
    v0.x = (v0.x - mu) * inv * g0.x + b0.x; v0.y = (v0.y - mu) * inv * g0.y + b0.y;
    v0.z = (v0.z - mu) * inv * g0.z + b0.z; v0.w = (v0.w - mu) * inv * g0.w + b0.w;
    v1.x = (v1.x - mu) * inv * g1.x + b1.x; v1.y = (v1.y - mu) * inv * g1.y + b1.y;
    v1.z = (v1.z - mu) * inv * g1.z + b1.z; v1.w = (v1.w - mu) * inv * g1.w + b1.w;

    float4 w00 = *(const float4*)(Wpred + c),      w01 = *(const float4*)(Wpred + c + 4);
    float4 w10 = *(const float4*)(Wpred + CH + c), w11 = *(const float4*)(Wpred + CH + c + 4);
    float d0 = v0.x * w00.x + v0.y * w00.y + v0.z * w00.z + v0.w * w00.w +
               v1.x * w01.x + v1.y * w01.y + v1.z * w01.z + v1.w * w01.w;
    float d1 = v0.x * w10.x + v0.y * w10.y + v0.z * w10.z + v0.w * w10.w +
               v1.x * w11.x + v1.y * w11.y + v1.z * w11.z + v1.w * w11.w;
    #pragma unroll
    for (int o = 16; o; o >>= 1) {
        d0 += __shfl_xor_sync(0xffffffffu, d0, o);
        d1 += __shfl_xor_sync(0xffffffffu, d1, o);
    }
    float* ox = out_x + (size_t)b * CH * NP + n;
    ox[(size_t)(c + 0) * NP] = v0.x; ox[(size_t)(c + 1) * NP] = v0.y;
    ox[(size_t)(c + 2) * NP] = v0.z; ox[(size_t)(c + 3) * NP] = v0.w;
    ox[(size_t)(c + 4) * NP] = v1.x; ox[(size_t)(c + 5) * NP] = v1.y;
    ox[(size_t)(c + 6) * NP] = v1.z; ox[(size_t)(c + 7) * NP] = v1.w;
    if (lane == 0) {
        float2 pp = ((const float2*)ppos)[b * NP + n];
        float c0 = d0 + bpred[0] + pp.x;
        float c1 = d1 + bpred[1] + pp.y;
        out_c[(size_t)b * 2 * NP + n] = c0;
        out_c[(size_t)b * 2 * NP + NP + n] = c1;
        ((float2*)out_np)[b * NP + n] = make_float2(c0, c1);
    }
}

// ---------------- launch ----------------
extern "C" void kernel_launch(void* const* d_in, const int* in_sizes, int n_in,
                              void* d_out, int out_size) {
    const float* ptsf   = (const float*)d_in[0];
    const float* ppos   = (const float*)d_in[1];
    const float* imgf   = (const float*)d_in[2];
    const float* ipos   = (const float*)d_in[3];
    const float* ptscls = (const float*)d_in[4];
    const float* imgcls = (const float*)d_in[5];
    const float* Wp  = (const float*)d_in[6];  const float* bp  = (const float*)d_in[7];
    const float* Wi  = (const float*)d_in[8];  const float* bi  = (const float*)d_in[9];
    const float* Wqp = (const float*)d_in[10]; const float* bqp = (const float*)d_in[11];
    const float* Wkp = (const float*)d_in[12]; const float* bkp = (const float*)d_in[13];
    const float* Wout = (const float*)d_in[14]; const float* bout = (const float*)d_in[15];
    const float* gout = (const float*)d_in[16]; const float* betaout = (const float*)d_in[17];
    const float* Wf1 = (const float*)d_in[18]; const float* bf1 = (const float*)d_in[19];
    const float* Wf2 = (const float*)d_in[20]; const float* bf2 = (const float*)d_in[21];
    const float* gln = (const float*)d_in[22]; const float* bln = (const float*)d_in[23];
    const float* Wpred = (const float*)d_in[24]; const float* bpred = (const float*)d_in[25];

    float* out    = (float*)d_out;
    float* out_x  = out;                                   // [2,256,2048]
    float* out_np = out + (size_t)BSZ * CH * NP;           // [2,2048,2]
    float* out_c  = out_np + (size_t)BSZ * NP * 2;         // [2,2,2048]

    const int IPOT_SMEM = NP * (int)sizeof(float) + 8 * NP * (int)sizeof(__half);  // 40 KB
    cudaFuncSetAttribute(k_ipot_persist, cudaFuncAttributeMaxDynamicSharedMemorySize, IPOT_SMEM);

    dim3 tb(32, 8);
    k_cls<<<NROW / 256, 256>>>(ptscls, imgcls);                    // launch 1
    k_transpose<<<dim3(NP / 32, CH / 32, BSZ), tb>>>(ptsf, 0);     // launch 2
    k_transpose<<<dim3(NP / 32, CH / 32, BSZ), tb>>>(imgf, 1);     // launch 3

    // launch 4 (ncu capture slot): ALL 100 IPOT iterations + b_final + rownorm
    k_ipot_persist<<<NBLK, 256, IPOT_SMEM>>>(ppos, ipos);

    // projections + positional embeddings
    k_gemm<0><<<dim3(CH / 128, NP / 64, BSZ), 256>>>(Wp, bp, bqp, Wqp, ppos);
    k_gemm<1><<<dim3(NP / 128, CH / 64, BSZ), 256>>>(Wi, bi, bkp, Wkp, ipos);  // *bv folded

    // attention GEMM: img_att = w ⊙ (Q_fp16 @ imf_scaled^T)
    k_gemm<2><<<dim3(CH / 128, NP / 64, BSZ), 256>>>(nullptr, nullptr, nullptr, nullptr, nullptr);
    // out projection + LN
    k_gemm<3><<<dim3(CH / 128, NP / 64, BSZ), 256>>>(Wout, bout, nullptr, nullptr, nullptr);
    k_ln<<<NROW / 8, 256>>>(gout, betaout);
    // FFN
    k_gemm<4><<<dim3(FFNC / 128, NP / 64, BSZ), 256>>>(Wf1, bf1, nullptr, nullptr, nullptr);
    k_gemm<5><<<dim3(CH / 128, NP / 64, BSZ), 256>>>(Wf2, bf2, nullptr, nullptr, nullptr);
    // final LN + head + outputs
    k_final<<<NROW / 8, 256>>>(gln, bln, Wpred, bpred, ppos, out_x, out_np, out_c);
}